// round 10
// baseline (speedup 1.0000x reference)
#include <cuda_runtime.h>
#include <cstdint>
#include <math.h>

#define N 8192
#define S1 4            // j-splits per pass
#define NIB 64          // i-blocks of 128 rows
#define JR (N/S1)       // 2048 j per CTA
#define KT 256          // j staged per tile
#define NT (JR/KT)      // 8 tiles
#define RS 272          // SMEM B row stride bytes (256 + 16 pad) -> conflict-free

#define QS1 (16383.0f/12.0f)
#define DQ1 (12.0f/16383.0f)
#define QS2 (16383.0f/60.0f)
#define DQ2 (60.0f/16383.0f)

// -------- scratch (static device globals; no allocation) --------
__device__ signed char g_q1hi[(size_t)32*N];   // [n][j]
__device__ signed char g_q1lo[(size_t)32*N];
__device__ signed char g_q2hi[(size_t)8*N];    // [n][j]
__device__ signed char g_q2lo[(size_t)8*N];
__device__ float g_invrow[N];
__device__ int   g_part1[(size_t)S1*N*32];     // s32 partials (128*hi + lo)
__device__ int   g_cnt1[(size_t)S1*N];
__device__ int   g_part2[(size_t)S1*N*8];

// ===================== helpers =====================
__device__ __forceinline__ unsigned long long pk2(float lo, float hi) {
    unsigned long long r;
    asm("mov.b64 %0, {%1, %2};" : "=l"(r) : "f"(lo), "f"(hi));
    return r;
}
__device__ __forceinline__ unsigned long long bc2(float x) { return pk2(x, x); }
__device__ __forceinline__ unsigned long long fma2(unsigned long long a, unsigned long long b, unsigned long long c) {
    unsigned long long r; asm("fma.rn.f32x2 %0,%1,%2,%3;" : "=l"(r) : "l"(a), "l"(b), "l"(c)); return r;
}
__device__ __forceinline__ unsigned long long add2(unsigned long long a, unsigned long long b) {
    unsigned long long r; asm("add.rn.f32x2 %0,%1,%2;" : "=l"(r) : "l"(a), "l"(b)); return r;
}
// diff = pi . pj + (P.w + tcn)  where P.w = (6.25 - |pj|^2)/2, tcn = -|pi|^2/2
// diff > 0  <=>  dist^2 < 6.25
__device__ __forceinline__ unsigned long long diffp(
    unsigned long long px, unsigned long long py, unsigned long long pz,
    unsigned long long tcn, const ulonglong4& P) {
    return fma2(px, P.x, fma2(py, P.y, fma2(pz, P.z, add2(P.w, tcn))));
}
// pack 4 mask bytes (0/1) from two packed diffs (4 compares vs 0)
__device__ __forceinline__ uint32_t apack(unsigned long long dA, unsigned long long dB) {
    float f0, f1, f2, f3; uint32_t s0, s1, s2, s3;
    asm("mov.b64 {%0,%1}, %2;" : "=f"(f0), "=f"(f1) : "l"(dA));
    asm("mov.b64 {%0,%1}, %2;" : "=f"(f2), "=f"(f3) : "l"(dB));
    asm("set.gt.u32.f32 %0, %1, %2;" : "=r"(s0) : "f"(f0), "f"(0.0f));
    asm("set.gt.u32.f32 %0, %1, %2;" : "=r"(s1) : "f"(f1), "f"(0.0f));
    asm("set.gt.u32.f32 %0, %1, %2;" : "=r"(s2) : "f"(f2), "f"(0.0f));
    asm("set.gt.u32.f32 %0, %1, %2;" : "=r"(s3) : "f"(f3), "f"(0.0f));
    return (s0 & 1u) | (s1 & 0x100u) | (s2 & 0x10000u) | (s3 & 0x1000000u);
}
#define IMMA16832(d, a, b0v, b1v) asm volatile( \
    "mma.sync.aligned.m16n8k32.row.col.s32.s8.s8.s32 " \
    "{%0,%1,%2,%3}, {%4,%5,%6,%7}, {%8,%9}, {%0,%1,%2,%3};" \
    : "+r"((d)[0]),"+r"((d)[1]),"+r"((d)[2]),"+r"((d)[3]) \
    : "r"((a)[0]),"r"((a)[1]),"r"((a)[2]),"r"((a)[3]), "r"(b0v),"r"(b1v))
#define ONES8 0x01010101u

// packed j-pair entry: {x,x'},{y,y'},{z,z'},{(6.25-c)/2, (6.25-c')/2}
__device__ __forceinline__ ulonglong4 make_pair(float4 a, float4 b) {
    float ca = fmaf(a.x, a.x, fmaf(a.y, a.y, a.z*a.z));
    float cb = fmaf(b.x, b.x, fmaf(b.y, b.y, b.z*b.z));
    ulonglong4 r;
    r.x = pk2(a.x, b.x);
    r.y = pk2(a.y, b.y);
    r.z = pk2(a.z, b.z);
    r.w = pk2((6.25f - ca)*0.5f, (6.25f - cb)*0.5f);
    return r;
}
__device__ __forceinline__ void quant2(float v, float qs, signed char& hi, signed char& lo) {
    int Q = __float2int_rn(v * qs);
    int h = Q >> 7;
    hi = (signed char)h;
    lo = (signed char)(Q - (h << 7));
}

// ---------------- kernel 1: features + y1 = x@W1 + b1, quantize [n][j] ----------------
__global__ void feat_kernel(const float4* __restrict__ led, const float* __restrict__ B,
                            const float* __restrict__ emb, const float* __restrict__ W1,
                            const float* __restrict__ b1) {
    __shared__ float sB[48], semb[104], sW1[40*32], sb1[32];
    int t = threadIdx.x;
    if (t < 48)  sB[t]   = B[t];
    if (t < 104) semb[t] = emb[t];
    if (t < 32)  sb1[t]  = b1[t];
    for (int idx = t; idx < 40*32; idx += 128) sW1[idx] = W1[idx];
    __syncthreads();

    int i = blockIdx.x*128 + t;
    float4 p = led[i];
    float x[40];
    #pragma unroll
    for (int f = 0; f < 16; f++) {
        float pr = (p.x*sB[f] + p.y*sB[16+f] + p.z*sB[32+f]) * 6.283185307179586f;
        float sv, cv; sincosf(pr, &sv, &cv);
        x[f] = sv; x[16+f] = cv;
    }
    int fr = (int)p.w;
    #pragma unroll
    for (int e = 0; e < 8; e++) x[32+e] = semb[fr*8 + e];

    #pragma unroll 4
    for (int k = 0; k < 32; k++) {
        float acc = sb1[k];
        #pragma unroll
        for (int d = 0; d < 40; d++) acc = fmaf(x[d], sW1[d*32 + k], acc);
        signed char hi, lo;
        quant2(acc, QS1, hi, lo);
        g_q1hi[(size_t)k*N + i] = hi;
        g_q1lo[(size_t)k*N + i] = lo;
    }
}

// ---------------- kernel 2: pass 1 — IMMA masked GEMM (n=32) + counts ----------------
__global__ void __launch_bounds__(256, 2) pass1_mma(const float4* __restrict__ led) {
    __shared__ __align__(16) char sQhi[32*RS];       // 8.5KB
    __shared__ __align__(16) char sQlo[32*RS];       // 8.5KB
    __shared__ __align__(16) ulonglong4 s_pj[KT/2];  // 4KB

    int t = threadIdx.x, lane = t & 31, wid = t >> 5;
    int ib = blockIdx.x, s = blockIdx.y;
    int q = lane & 3, g = lane >> 2;
    int i0 = ib*128 + wid*16 + g;                 // rows i0, i0+8
    float4 pi0 = led[i0], pi1 = led[i0 + 8];

    unsigned long long px0 = bc2(pi0.x), py0 = bc2(pi0.y), pz0 = bc2(pi0.z);
    unsigned long long px1 = bc2(pi1.x), py1 = bc2(pi1.y), pz1 = bc2(pi1.z);
    unsigned long long tcn0 = bc2(-0.5f*fmaf(pi0.x, pi0.x, fmaf(pi0.y, pi0.y, pi0.z*pi0.z)));
    unsigned long long tcn1 = bc2(-0.5f*fmaf(pi1.x, pi1.x, fmaf(pi1.y, pi1.y, pi1.z*pi1.z)));

    int dh[4][4] = {}, dl[4][4] = {}, dcnt[4] = {};

    uint32_t boff = (uint32_t)(g*RS + 4*q);

    for (int tile = 0; tile < NT; tile++) {
        int j0 = s*JR + tile*KT;
        __syncthreads();
        // stage B digits: 32 rows x 256B each (16B chunks), 512 chunks per digit
        #pragma unroll
        for (int r2 = 0; r2 < 2; r2++) {
            int c = t + r2*256;
            int n = c >> 4, ch = c & 15;
            *(uint4*)(sQhi + n*RS + ch*16) = *(const uint4*)(g_q1hi + (size_t)n*N + j0 + ch*16);
            *(uint4*)(sQlo + n*RS + ch*16) = *(const uint4*)(g_q1lo + (size_t)n*N + j0 + ch*16);
        }
        if (t < KT/2) s_pj[t] = make_pair(led[j0 + 2*t], led[j0 + 2*t + 1]);
        __syncthreads();

        #pragma unroll
        for (int kc = 0; kc < KT/32; kc++) {
            int p0 = kc*16 + 2*q;
            ulonglong4 Pa = s_pj[p0], Pb = s_pj[p0 + 1];
            ulonglong4 Pc = s_pj[p0 + 8], Pd = s_pj[p0 + 9];

            uint32_t a[4];
            a[0] = apack(diffp(px0,py0,pz0,tcn0,Pa), diffp(px0,py0,pz0,tcn0,Pb));
            a[1] = apack(diffp(px1,py1,pz1,tcn1,Pa), diffp(px1,py1,pz1,tcn1,Pb));
            a[2] = apack(diffp(px0,py0,pz0,tcn0,Pc), diffp(px0,py0,pz0,tcn0,Pd));
            a[3] = apack(diffp(px1,py1,pz1,tcn1,Pc), diffp(px1,py1,pz1,tcn1,Pd));

            uint32_t koff = boff + (uint32_t)(kc*32);
            uint32_t off0 = koff;            // k 4q..4q+3
            uint32_t off1 = koff + 16;       // k 16+4q..
            #pragma unroll
            for (int m = 0; m < 4; m++) {
                uint32_t ro = (uint32_t)(8*m*RS);
                uint32_t bh0 = *(const uint32_t*)(sQhi + ro + off0);
                uint32_t bh1 = *(const uint32_t*)(sQhi + ro + off1);
                IMMA16832(dh[m], a, bh0, bh1);
                uint32_t bl0 = *(const uint32_t*)(sQlo + ro + off0);
                uint32_t bl1 = *(const uint32_t*)(sQlo + ro + off1);
                IMMA16832(dl[m], a, bl0, bl1);
            }
            IMMA16832(dcnt, a, ONES8, ONES8);
        }
    }

    int* d0 = &g_part1[((size_t)s*N + i0)*32];
    int* d1 = d0 + 8*32;
    #pragma unroll
    for (int m = 0; m < 4; m++) {
        *(int2*)(d0 + 8*m + 2*q) = make_int2(dh[m][0]*128 + dl[m][0], dh[m][1]*128 + dl[m][1]);
        *(int2*)(d1 + 8*m + 2*q) = make_int2(dh[m][2]*128 + dl[m][2], dh[m][3]*128 + dl[m][3]);
    }
    if (q == 0) {
        g_cnt1[(size_t)s*N + i0]     = dcnt[0];
        g_cnt1[(size_t)s*N + i0 + 8] = dcnt[2];
    }
}

// ---------------- kernel 3: reduce -> h (smem) -> y2 -> quantize [n][j] ----------------
__global__ void reduce1_y2(const float* __restrict__ W2, const float* __restrict__ b2) {
    __shared__ float sh[8*32];
    int t = threadIdx.x, b = blockIdx.x;
    int idx = b*256 + t;           // N*32 total
    int i = idx >> 5, k = idx & 31;
    int ssum = 0;
    #pragma unroll
    for (int s = 0; s < S1; s++) ssum += g_part1[(size_t)s*N*32 + idx];
    int c = 0;
    #pragma unroll
    for (int s = 0; s < S1; s++) c += g_cnt1[(size_t)s*N + i];
    float inv = 1.0f / ((float)c + 1e-6f);
    float h = (float)ssum * DQ1 * inv;
    h = h > 0.0f ? h : 0.0f;
    sh[t] = h;
    if (k == 0) g_invrow[i] = inv;
    __syncthreads();

    if (t < 64) {
        int row = t >> 3, kk = t & 7;
        float a = b2[kk];
        #pragma unroll
        for (int d = 0; d < 32; d++) a = fmaf(sh[row*32 + d], W2[d*8 + kk], a);
        signed char hi, lo;
        quant2(a, QS2, hi, lo);
        int ig = b*8 + row;
        g_q2hi[(size_t)kk*N + ig] = hi;
        g_q2lo[(size_t)kk*N + ig] = lo;
    }
}

// ---------------- kernel 4: pass 2 — IMMA masked GEMM (n=8) ----------------
__global__ void __launch_bounds__(256, 2) pass2_mma(const float4* __restrict__ led) {
    __shared__ __align__(16) char sQhi[8*RS];
    __shared__ __align__(16) char sQlo[8*RS];
    __shared__ __align__(16) ulonglong4 s_pj[KT/2];

    int t = threadIdx.x, lane = t & 31, wid = t >> 5;
    int ib = blockIdx.x, s = blockIdx.y;
    int q = lane & 3, g = lane >> 2;
    int i0 = ib*128 + wid*16 + g;
    float4 pi0 = led[i0], pi1 = led[i0 + 8];

    unsigned long long px0 = bc2(pi0.x), py0 = bc2(pi0.y), pz0 = bc2(pi0.z);
    unsigned long long px1 = bc2(pi1.x), py1 = bc2(pi1.y), pz1 = bc2(pi1.z);
    unsigned long long tcn0 = bc2(-0.5f*fmaf(pi0.x, pi0.x, fmaf(pi0.y, pi0.y, pi0.z*pi0.z)));
    unsigned long long tcn1 = bc2(-0.5f*fmaf(pi1.x, pi1.x, fmaf(pi1.y, pi1.y, pi1.z*pi1.z)));

    int dh[4] = {}, dl[4] = {};
    uint32_t boff = (uint32_t)(g*RS + 4*q);

    for (int tile = 0; tile < NT; tile++) {
        int j0 = s*JR + tile*KT;
        __syncthreads();
        if (t < 128) {
            int n = t >> 4, ch = t & 15;
            *(uint4*)(sQhi + n*RS + ch*16) = *(const uint4*)(g_q2hi + (size_t)n*N + j0 + ch*16);
            s_pj[t] = make_pair(led[j0 + 2*t], led[j0 + 2*t + 1]);
        } else {
            int c = t - 128;
            int n = c >> 4, ch = c & 15;
            *(uint4*)(sQlo + n*RS + ch*16) = *(const uint4*)(g_q2lo + (size_t)n*N + j0 + ch*16);
        }
        __syncthreads();

        #pragma unroll
        for (int kc = 0; kc < KT/32; kc++) {
            int p0 = kc*16 + 2*q;
            ulonglong4 Pa = s_pj[p0], Pb = s_pj[p0 + 1];
            ulonglong4 Pc = s_pj[p0 + 8], Pd = s_pj[p0 + 9];

            uint32_t a[4];
            a[0] = apack(diffp(px0,py0,pz0,tcn0,Pa), diffp(px0,py0,pz0,tcn0,Pb));
            a[1] = apack(diffp(px1,py1,pz1,tcn1,Pa), diffp(px1,py1,pz1,tcn1,Pb));
            a[2] = apack(diffp(px0,py0,pz0,tcn0,Pc), diffp(px0,py0,pz0,tcn0,Pd));
            a[3] = apack(diffp(px1,py1,pz1,tcn1,Pc), diffp(px1,py1,pz1,tcn1,Pd));

            uint32_t off0 = boff + (uint32_t)(kc*32);
            uint32_t bh0 = *(const uint32_t*)(sQhi + off0);
            uint32_t bh1 = *(const uint32_t*)(sQhi + off0 + 16);
            IMMA16832(dh, a, bh0, bh1);
            uint32_t bl0 = *(const uint32_t*)(sQlo + off0);
            uint32_t bl1 = *(const uint32_t*)(sQlo + off0 + 16);
            IMMA16832(dl, a, bl0, bl1);
        }
    }

    int* d0 = &g_part2[((size_t)s*N + i0)*8];
    *(int2*)(d0 + 2*q)        = make_int2(dh[0]*128 + dl[0], dh[1]*128 + dl[1]);
    *(int2*)(d0 + 8*8 + 2*q)  = make_int2(dh[2]*128 + dl[2], dh[3]*128 + dl[3]);
}

// ---------------- kernel 5: reduce + relu -> out ----------------
__global__ void reduce2_kernel(float* __restrict__ out) {
    int idx = blockIdx.x*256 + threadIdx.x;   // N*8
    int i = idx >> 3;
    int sum = 0;
    #pragma unroll
    for (int s = 0; s < S1; s++) sum += g_part2[(size_t)s*N*8 + idx];
    float v = (float)sum * DQ2 * g_invrow[i];
    out[idx] = v > 0.0f ? v : 0.0f;
}

// ---------------- launch ----------------
extern "C" void kernel_launch(void* const* d_in, const int* in_sizes, int n_in,
                              void* d_out, int out_size) {
    const float4* led = (const float4*)d_in[0];
    const float*  B   = (const float*)d_in[1];
    const float*  emb = (const float*)d_in[2];
    const float*  W1  = (const float*)d_in[3];
    const float*  b1  = (const float*)d_in[4];
    const float*  W2  = (const float*)d_in[5];
    const float*  b2  = (const float*)d_in[6];
    float* out = (float*)d_out;

    feat_kernel<<<64, 128>>>(led, B, emb, W1, b1);
    pass1_mma<<<dim3(NIB, S1), 256>>>(led);
    reduce1_y2<<<N*32/256, 256>>>(W2, b2);
    pass2_mma<<<dim3(NIB, S1), 256>>>(led);
    reduce2_kernel<<<N*8/256, 256>>>(out);
}

// round 11
// speedup vs baseline: 1.2918x; 1.2918x over previous
#include <cuda_runtime.h>
#include <cuda_fp16.h>
#include <cstdint>
#include <math.h>

#define N 8192
#define S1 4            // j-splits per GEMM pass / mask kernel
#define NIB 64          // i-blocks of 128 rows
#define JR 2048         // j per CTA per pass
#define KT 128          // j staged per B tile
#define NT 16           // tiles per pass (JR/KT)
#define RS 272          // SMEM B row stride bytes (128*2 + 16 pad)

// -------- scratch (static device globals; no allocation) --------
__device__ __half   g_y1h[(size_t)32*N];            // [n][j] 512KB
__device__ __half   g_y2h[(size_t)8*N];             // [n][j] 128KB
__device__ uint32_t g_W[(size_t)256*64*8*16];       // [chunk][ib][warp][m] ballot words, 8MB
__device__ int      g_cntM[(size_t)S1*N];           // partial row counts
__device__ float    g_invrow[N];
__device__ float    g_part1[(size_t)S1*N*32];       // 4MB fp32 partials
__device__ float    g_part2[(size_t)S1*N*8];

// ===================== helpers =====================
__device__ __forceinline__ uint32_t smem_u32(const void* p) {
    uint32_t a;
    asm("{ .reg .u64 t; cvta.to.shared.u64 t, %1; cvt.u32.u64 %0, t; }" : "=r"(a) : "l"(p));
    return a;
}
// expand 2 mask bits -> packed fp16x2 {bit0 ? 1.0 : 0, bit1 ? 1.0 : 0}
__device__ __forceinline__ uint32_t amask(uint32_t v) {
    return (v & 1u)*0x3C00u + ((v >> 1) & 1u)*0x3C000000u;
}
#define MMA16816(d, a, b0v, b1v) asm volatile( \
    "mma.sync.aligned.m16n8k16.row.col.f32.f16.f16.f32 " \
    "{%0,%1,%2,%3}, {%4,%5,%6,%7}, {%8,%9}, {%0,%1,%2,%3};" \
    : "+f"((d)[0]),"+f"((d)[1]),"+f"((d)[2]),"+f"((d)[3]) \
    : "r"((a)[0]),"r"((a)[1]),"r"((a)[2]),"r"((a)[3]), "r"(b0v),"r"(b1v))
#define LDSM_X4(r0,r1,r2,r3, addr) asm volatile( \
    "ldmatrix.sync.aligned.m8n8.x4.shared.b16 {%0,%1,%2,%3}, [%4];" \
    : "=r"(r0),"=r"(r1),"=r"(r2),"=r"(r3) : "r"(addr))

// ---------------- kernel 1: features + y1 = x@W1 + b1 -> fp16 [n][j] ----------------
__global__ void feat_kernel(const float4* __restrict__ led, const float* __restrict__ B,
                            const float* __restrict__ emb, const float* __restrict__ W1,
                            const float* __restrict__ b1) {
    __shared__ float sB[48], semb[104], sW1[40*32], sb1[32];
    int t = threadIdx.x;
    if (t < 48)  sB[t]   = B[t];
    if (t < 104) semb[t] = emb[t];
    if (t < 32)  sb1[t]  = b1[t];
    for (int idx = t; idx < 40*32; idx += 128) sW1[idx] = W1[idx];
    __syncthreads();

    int i = blockIdx.x*128 + t;
    float4 p = led[i];
    float x[40];
    #pragma unroll
    for (int f = 0; f < 16; f++) {
        float pr = (p.x*sB[f] + p.y*sB[16+f] + p.z*sB[32+f]) * 6.283185307179586f;
        float sv, cv; sincosf(pr, &sv, &cv);
        x[f] = sv; x[16+f] = cv;
    }
    int fr = (int)p.w;
    #pragma unroll
    for (int e = 0; e < 8; e++) x[32+e] = semb[fr*8 + e];

    #pragma unroll 4
    for (int k = 0; k < 32; k++) {
        float acc = sb1[k];
        #pragma unroll
        for (int d = 0; d < 40; d++) acc = fmaf(x[d], sW1[d*32 + k], acc);
        g_y1h[(size_t)k*N + i] = __float2half(acc);
    }
}

// ---------------- kernel 2: mask kernel — ballot-transposed bitmask + exact counts ----------------
// warp owns 16 i-rows; lane owns one j per 32-j chunk. W word m = j-bits for i-row m.
__global__ void __launch_bounds__(256) mask_kernel(const float4* __restrict__ led) {
    __shared__ uint32_t s_W[8*16];
    int t = threadIdx.x, lane = t & 31, w = t >> 5;
    int ib = blockIdx.x, js = blockIdx.y;
    int i0g = ib*128 + w*16;

    float px[16], py[16], pz[16], cim[16];
    #pragma unroll
    for (int m = 0; m < 16; m++) {
        float4 p = led[i0g + m];
        px[m] = p.x; py[m] = p.y; pz[m] = p.z;
        cim[m] = 3.125f - 0.5f*fmaf(p.x, p.x, fmaf(p.y, p.y, p.z*p.z));
    }
    int cnt = 0;

    for (int c = js*64; c < js*64 + 64; c++) {
        float4 pj = led[c*32 + lane];
        float cj = -0.5f*fmaf(pj.x, pj.x, fmaf(pj.y, pj.y, pj.z*pj.z));
        #pragma unroll
        for (int m = 0; m < 16; m++) {
            // d > 0  <=>  dist^2(i_m, j) < 6.25   (i==j: d = 3.125 > 0 -> mask 1, matches ref)
            float d = fmaf(pj.x, px[m], fmaf(pj.y, py[m], fmaf(pj.z, pz[m], cim[m] + cj)));
            unsigned Wm = __ballot_sync(0xffffffffu, d > 0.0f);
            if (lane == m) cnt += __popc(Wm);
            if (lane == 0) s_W[w*16 + m] = Wm;
        }
        __syncwarp();
        if (lane < 16)
            g_W[(((size_t)c*64 + ib)*8 + w)*16 + lane] = s_W[w*16 + lane];
        __syncwarp();
    }
    if (lane < 16) g_cntM[(size_t)js*N + i0g + lane] = cnt;
}

// ---------------- kernel 3: pass 1 — HMMA masked GEMM (n=32), bit-fed A ----------------
__global__ void __launch_bounds__(256, 2) pass1_mma() {
    __shared__ __align__(16) char sBh[32*RS];    // 8.5KB fp16 B tile

    int t = threadIdx.x, lane = t & 31, wid = t >> 5;
    int ib = blockIdx.x, s = blockIdx.y;
    int q = lane & 3, g = lane >> 2;
    int i0 = ib*128 + wid*16 + g;

    float dacc[4][4] = {};

    int sel = lane >> 3, lrow = lane & 7;
    uint32_t hA = smem_u32(sBh) + (uint32_t)(((sel >> 1)*8 + lrow)*RS + (sel & 1)*16);
    uint32_t hB = hA + 16*RS;

    for (int tile = 0; tile < NT; tile++) {
        int j0 = s*JR + tile*KT;
        int c0 = j0 >> 5;
        __syncthreads();
        // stage B: 32 rows x 256B = 512 uint4, 2 per thread
        #pragma unroll
        for (int r2 = 0; r2 < 2; r2++) {
            int c = t + r2*256;
            int n = c >> 4, ch = c & 15;
            *(uint4*)(sBh + n*RS + ch*16) = *(const uint4*)(g_y1h + (size_t)n*N + j0 + ch*8);
        }
        __syncthreads();

        uint32_t wg[4], wg8[4];
        #pragma unroll
        for (int cc = 0; cc < 4; cc++) {
            size_t base = (((size_t)(c0 + cc)*64 + ib)*8 + wid)*16;
            wg[cc]  = g_W[base + g];
            wg8[cc] = g_W[base + g + 8];
        }

        #pragma unroll
        for (int cc = 0; cc < 4; cc++) {
            #pragma unroll
            for (int hc = 0; hc < 2; hc++) {
                int kc = cc*2 + hc;
                uint32_t vg  = wg[cc]  >> (hc*16 + 2*q);
                uint32_t vg8 = wg8[cc] >> (hc*16 + 2*q);
                uint32_t a[4] = { amask(vg), amask(vg8), amask(vg >> 8), amask(vg8 >> 8) };

                uint32_t koff = (uint32_t)(kc*32);
                uint32_t h0,h1,h2,h3, h4,h5,h6,h7;
                LDSM_X4(h0,h1,h2,h3, hA + koff);
                LDSM_X4(h4,h5,h6,h7, hB + koff);
                MMA16816(dacc[0], a, h0, h1);
                MMA16816(dacc[1], a, h2, h3);
                MMA16816(dacc[2], a, h4, h5);
                MMA16816(dacc[3], a, h6, h7);
            }
        }
    }

    float* d0 = &g_part1[((size_t)s*N + i0)*32];
    float* d1 = d0 + 8*32;
    #pragma unroll
    for (int m = 0; m < 4; m++) {
        *(float2*)(d0 + 8*m + 2*q) = make_float2(dacc[m][0], dacc[m][1]);
        *(float2*)(d1 + 8*m + 2*q) = make_float2(dacc[m][2], dacc[m][3]);
    }
}

// ---------------- kernel 4: reduce -> h -> y2 -> fp16 [n][j] ----------------
__global__ void reduce1_y2(const float* __restrict__ W2, const float* __restrict__ b2) {
    __shared__ float sh[256];
    int t = threadIdx.x, b = blockIdx.x;
    int idx = b*256 + t;           // N*32 total
    int i = idx >> 5, k = idx & 31;
    float sum = 0.0f;
    #pragma unroll
    for (int s = 0; s < S1; s++) sum += g_part1[(size_t)s*N*32 + idx];
    int c = 0;
    #pragma unroll
    for (int s = 0; s < S1; s++) c += g_cntM[(size_t)s*N + i];
    float inv = 1.0f / ((float)c + 1e-6f);
    float h = sum * inv;
    sh[t] = h > 0.0f ? h : 0.0f;
    if (k == 0) g_invrow[i] = inv;
    __syncthreads();

    if (t < 64) {
        int row = t >> 3, kk = t & 7;
        float a = b2[kk];
        #pragma unroll
        for (int d = 0; d < 32; d++) a = fmaf(sh[row*32 + d], W2[d*8 + kk], a);
        g_y2h[(size_t)kk*N + b*8 + row] = __float2half(a);
    }
}

// ---------------- kernel 5: pass 2 — HMMA masked GEMM (n=8), bit-fed A ----------------
__global__ void __launch_bounds__(256, 2) pass2_mma() {
    __shared__ __align__(16) char sBh[8*RS];

    int t = threadIdx.x, lane = t & 31, wid = t >> 5;
    int ib = blockIdx.x, s = blockIdx.y;
    int q = lane & 3, g = lane >> 2;
    int i0 = ib*128 + wid*16 + g;

    float dacc[4] = {};

    int sel = lane >> 3, lrow = lane & 7;
    uint32_t bAddr = smem_u32(sBh) + (uint32_t)(lrow*RS + sel*16);

    for (int tile = 0; tile < NT; tile++) {
        int j0 = s*JR + tile*KT;
        int c0 = j0 >> 5;
        __syncthreads();
        if (t < 128) {
            int n = t >> 4, ch = t & 15;
            *(uint4*)(sBh + n*RS + ch*16) = *(const uint4*)(g_y2h + (size_t)n*N + j0 + ch*8);
        }
        __syncthreads();

        uint32_t wg[4], wg8[4];
        #pragma unroll
        for (int cc = 0; cc < 4; cc++) {
            size_t base = (((size_t)(c0 + cc)*64 + ib)*8 + wid)*16;
            wg[cc]  = g_W[base + g];
            wg8[cc] = g_W[base + g + 8];
        }

        #pragma unroll
        for (int cc = 0; cc < 4; cc++) {
            uint32_t r0, r1, r2, r3;
            LDSM_X4(r0, r1, r2, r3, bAddr + (uint32_t)(cc*64));
            #pragma unroll
            for (int hc = 0; hc < 2; hc++) {
                uint32_t vg  = wg[cc]  >> (hc*16 + 2*q);
                uint32_t vg8 = wg8[cc] >> (hc*16 + 2*q);
                uint32_t a[4] = { amask(vg), amask(vg8), amask(vg >> 8), amask(vg8 >> 8) };
                if (hc == 0) { MMA16816(dacc, a, r0, r1); }
                else         { MMA16816(dacc, a, r2, r3); }
            }
        }
    }

    float* d0 = &g_part2[((size_t)s*N + i0)*8];
    *(float2*)(d0 + 2*q)       = make_float2(dacc[0], dacc[1]);
    *(float2*)(d0 + 64 + 2*q)  = make_float2(dacc[2], dacc[3]);   // row i0+8
}

// ---------------- kernel 6: reduce + relu -> out ----------------
__global__ void reduce2_kernel(float* __restrict__ out) {
    int idx = blockIdx.x*256 + threadIdx.x;   // N*8
    int i = idx >> 3;
    float sum = 0.0f;
    #pragma unroll
    for (int s = 0; s < S1; s++) sum += g_part2[(size_t)s*N*8 + idx];
    float v = sum * g_invrow[i];
    out[idx] = v > 0.0f ? v : 0.0f;
}

// ---------------- launch ----------------
extern "C" void kernel_launch(void* const* d_in, const int* in_sizes, int n_in,
                              void* d_out, int out_size) {
    const float4* led = (const float4*)d_in[0];
    const float*  B   = (const float*)d_in[1];
    const float*  emb = (const float*)d_in[2];
    const float*  W1  = (const float*)d_in[3];
    const float*  b1  = (const float*)d_in[4];
    const float*  W2  = (const float*)d_in[5];
    const float*  b2  = (const float*)d_in[6];
    float* out = (float*)d_out;

    feat_kernel<<<64, 128>>>(led, B, emb, W1, b1);
    mask_kernel<<<dim3(NIB, S1), 256>>>(led);
    pass1_mma<<<dim3(NIB, S1), 256>>>();
    reduce1_y2<<<N*32/256, 256>>>(W2, b2);
    pass2_mma<<<dim3(NIB, S1), 256>>>();
    reduce2_kernel<<<N*8/256, 256>>>(out);
}

// round 12
// speedup vs baseline: 1.6914x; 1.3094x over previous
#include <cuda_runtime.h>
#include <cuda_fp16.h>
#include <cstdint>
#include <math.h>

#define N 8192
#define S1 4            // j-splits per pass
#define NIB 64          // i-blocks of 128 rows
#define JR 2048         // j per CTA per pass
#define KT 256          // pass1: j staged per B tile
#define NT 8            // pass1 tiles (JR/KT)
#define RS 528          // pass1 B row stride bytes (256*2 + 16)
#define KT2 128         // pass2 tile
#define NT2 16
#define RS2 272

// -------- scratch (static device globals; no allocation) --------
__device__ __half   g_y1h[(size_t)32*N];            // [n][j]
__device__ __half   g_y2h[(size_t)8*N];             // [n][j]
__device__ uint32_t g_W[(size_t)256*64*8*16];       // [chunk][ib][warp][m] ballot words, 8MB
__device__ int      g_cntM[(size_t)S1*N];           // partial row counts
__device__ float    g_invrow[N];
__device__ float    g_part1[(size_t)S1*N*32];       // fp32 partials
__device__ float    g_part2[(size_t)S1*N*8];

// ===================== helpers =====================
__device__ __forceinline__ uint32_t smem_u32(const void* p) {
    uint32_t a;
    asm("{ .reg .u64 t; cvta.to.shared.u64 t, %1; cvt.u32.u64 %0, t; }" : "=r"(a) : "l"(p));
    return a;
}
// expand 2 mask bits -> packed fp16x2 {bit0 ? 1.0 : 0, bit1 ? 1.0 : 0}
__device__ __forceinline__ uint32_t amask(uint32_t v) {
    return (v & 1u)*0x3C00u + ((v >> 1) & 1u)*0x3C000000u;
}
#define MMA16816(d, a, b0v, b1v) asm volatile( \
    "mma.sync.aligned.m16n8k16.row.col.f32.f16.f16.f32 " \
    "{%0,%1,%2,%3}, {%4,%5,%6,%7}, {%8,%9}, {%0,%1,%2,%3};" \
    : "+f"((d)[0]),"+f"((d)[1]),"+f"((d)[2]),"+f"((d)[3]) \
    : "r"((a)[0]),"r"((a)[1]),"r"((a)[2]),"r"((a)[3]), "r"(b0v),"r"(b1v))
#define LDSM_X4(r0,r1,r2,r3, addr) asm volatile( \
    "ldmatrix.sync.aligned.m8n8.x4.shared.b16 {%0,%1,%2,%3}, [%4];" \
    : "=r"(r0),"=r"(r1),"=r"(r2),"=r"(r3) : "r"(addr))

// ---------------- kernel 1: features + y1 = x@W1 + b1 -> fp16 [n][j] ----------------
__global__ void feat_kernel(const float4* __restrict__ led, const float* __restrict__ B,
                            const float* __restrict__ emb, const float* __restrict__ W1,
                            const float* __restrict__ b1) {
    __shared__ float sB[48], semb[104], sW1[40*32], sb1[32];
    int t = threadIdx.x;
    if (t < 48)  sB[t]   = B[t];
    if (t < 104) semb[t] = emb[t];
    if (t < 32)  sb1[t]  = b1[t];
    for (int idx = t; idx < 40*32; idx += 128) sW1[idx] = W1[idx];
    __syncthreads();

    int i = blockIdx.x*128 + t;
    float4 p = led[i];
    float x[40];
    #pragma unroll
    for (int f = 0; f < 16; f++) {
        float pr = (p.x*sB[f] + p.y*sB[16+f] + p.z*sB[32+f]) * 6.283185307179586f;
        float sv, cv; sincosf(pr, &sv, &cv);
        x[f] = sv; x[16+f] = cv;
    }
    int fr = (int)p.w;
    #pragma unroll
    for (int e = 0; e < 8; e++) x[32+e] = semb[fr*8 + e];

    #pragma unroll 4
    for (int k = 0; k < 32; k++) {
        float acc = sb1[k];
        #pragma unroll
        for (int d = 0; d < 40; d++) acc = fmaf(x[d], sW1[d*32 + k], acc);
        g_y1h[(size_t)k*N + i] = __float2half(acc);
    }
}

// ---------------- kernel 2: pass 1 — fused ballot-mask + HMMA GEMM (n=32) + counts + mask store ----------------
__global__ void __launch_bounds__(256, 2) pass1_mma(const float4* __restrict__ led) {
    __shared__ __align__(16) char sBh[32*RS];    // 16.9KB fp16 B tile

    int t = threadIdx.x, lane = t & 31, wid = t >> 5;
    int ib = blockIdx.x, s = blockIdx.y;
    int q = lane & 3, g = lane >> 2;
    int i0g = ib*128 + wid*16;        // warp's 16 i-rows
    int i0 = i0g + g;                 // fragment rows i0, i0+8

    // warp's row positions in registers
    float px[16], py[16], pz[16], cim[16];
    #pragma unroll
    for (int m = 0; m < 16; m++) {
        float4 p = led[i0g + m];
        px[m] = p.x; py[m] = p.y; pz[m] = p.z;
        cim[m] = 3.125f - 0.5f*fmaf(p.x, p.x, fmaf(p.y, p.y, p.z*p.z));
    }
    int cnt = 0;
    float dacc[4][4] = {};

    int sel = lane >> 3, lrow = lane & 7;
    uint32_t hA = smem_u32(sBh) + (uint32_t)(((sel >> 1)*8 + lrow)*RS + (sel & 1)*16);
    uint32_t hB = hA + 16*RS;

    for (int tile = 0; tile < NT; tile++) {
        int j0 = s*JR + tile*KT;
        __syncthreads();
        // stage B: 32 rows x 512B = 1024 uint4, 4 per thread
        #pragma unroll
        for (int r2 = 0; r2 < 4; r2++) {
            int c = t + r2*256;
            int n = c >> 5, ch = c & 31;
            *(uint4*)(sBh + n*RS + ch*16) = *(const uint4*)(g_y1h + (size_t)n*N + j0 + ch*8);
        }
        __syncthreads();

        #pragma unroll
        for (int cc = 0; cc < 8; cc++) {
            int jb = j0 + cc*32;
            // ---- 16 ballots: mask word m = predicate bits for row m over 32 j ----
            float4 pj = led[jb + lane];
            float cj = -0.5f*fmaf(pj.x, pj.x, fmaf(pj.y, pj.y, pj.z*pj.z));
            uint32_t myW = 0;
            #pragma unroll
            for (int m = 0; m < 16; m++) {
                float d = fmaf(pj.x, px[m], fmaf(pj.y, py[m], fmaf(pj.z, pz[m], cim[m] + cj)));
                unsigned Wm = __ballot_sync(0xffffffffu, d > 0.0f);
                if (lane == m) myW = Wm;
            }
            if (lane < 16) {
                cnt += __popc(myW);
                g_W[(((size_t)(jb >> 5)*64 + ib)*8 + wid)*16 + lane] = myW;
            }
            uint32_t Wg  = __shfl_sync(0xffffffffu, myW, g);
            uint32_t Wg8 = __shfl_sync(0xffffffffu, myW, g + 8);

            // ---- 2 kc of HMMA fed by the fresh bits ----
            #pragma unroll
            for (int hc = 0; hc < 2; hc++) {
                uint32_t vg  = Wg  >> (hc*16 + 2*q);
                uint32_t vg8 = Wg8 >> (hc*16 + 2*q);
                uint32_t a[4] = { amask(vg), amask(vg8), amask(vg >> 8), amask(vg8 >> 8) };

                uint32_t koff = (uint32_t)((cc*2 + hc)*32);
                uint32_t h0,h1,h2,h3, h4,h5,h6,h7;
                LDSM_X4(h0,h1,h2,h3, hA + koff);
                LDSM_X4(h4,h5,h6,h7, hB + koff);
                MMA16816(dacc[0], a, h0, h1);
                MMA16816(dacc[1], a, h2, h3);
                MMA16816(dacc[2], a, h4, h5);
                MMA16816(dacc[3], a, h6, h7);
            }
        }
    }

    float* d0 = &g_part1[((size_t)s*N + i0)*32];
    float* d1 = d0 + 8*32;
    #pragma unroll
    for (int m = 0; m < 4; m++) {
        *(float2*)(d0 + 8*m + 2*q) = make_float2(dacc[m][0], dacc[m][1]);
        *(float2*)(d1 + 8*m + 2*q) = make_float2(dacc[m][2], dacc[m][3]);
    }
    if (lane < 16) g_cntM[(size_t)s*N + i0g + lane] = cnt;
}

// ---------------- kernel 3: reduce -> h -> y2 -> fp16 [n][j] ----------------
__global__ void reduce1_y2(const float* __restrict__ W2, const float* __restrict__ b2) {
    __shared__ float sh[256];
    int t = threadIdx.x, b = blockIdx.x;
    int idx = b*256 + t;           // N*32 total
    int i = idx >> 5, k = idx & 31;
    float sum = 0.0f;
    #pragma unroll
    for (int s = 0; s < S1; s++) sum += g_part1[(size_t)s*N*32 + idx];
    int c = 0;
    #pragma unroll
    for (int s = 0; s < S1; s++) c += g_cntM[(size_t)s*N + i];
    float inv = 1.0f / ((float)c + 1e-6f);
    float h = sum * inv;
    sh[t] = h > 0.0f ? h : 0.0f;
    if (k == 0) g_invrow[i] = inv;
    __syncthreads();

    if (t < 64) {
        int row = t >> 3, kk = t & 7;
        float a = b2[kk];
        #pragma unroll
        for (int d = 0; d < 32; d++) a = fmaf(sh[row*32 + d], W2[d*8 + kk], a);
        g_y2h[(size_t)kk*N + b*8 + row] = __float2half(a);
    }
}

// ---------------- kernel 4: pass 2 — HMMA masked GEMM (n=8), bit-fed (profiled slot #4) ----------------
__global__ void __launch_bounds__(256, 2) pass2_mma() {
    __shared__ __align__(16) char sBh[8*RS2];

    int t = threadIdx.x, lane = t & 31, wid = t >> 5;
    int ib = blockIdx.x, s = blockIdx.y;
    int q = lane & 3, g = lane >> 2;
    int i0 = ib*128 + wid*16 + g;

    float dacc[4] = {};

    int sel = lane >> 3, lrow = lane & 7;
    uint32_t bAddr = smem_u32(sBh) + (uint32_t)(lrow*RS2 + sel*16);

    for (int tile = 0; tile < NT2; tile++) {
        int j0 = s*JR + tile*KT2;
        int c0 = j0 >> 5;
        __syncthreads();
        if (t < 128) {
            int n = t >> 4, ch = t & 15;
            *(uint4*)(sBh + n*RS2 + ch*16) = *(const uint4*)(g_y2h + (size_t)n*N + j0 + ch*8);
        }
        __syncthreads();

        uint32_t wg[4], wg8[4];
        #pragma unroll
        for (int cc = 0; cc < 4; cc++) {
            size_t base = (((size_t)(c0 + cc)*64 + ib)*8 + wid)*16;
            wg[cc]  = g_W[base + g];
            wg8[cc] = g_W[base + g + 8];
        }

        #pragma unroll
        for (int cc = 0; cc < 4; cc++) {
            uint32_t r0, r1, r2, r3;
            LDSM_X4(r0, r1, r2, r3, bAddr + (uint32_t)(cc*64));
            #pragma unroll
            for (int hc = 0; hc < 2; hc++) {
                uint32_t vg  = wg[cc]  >> (hc*16 + 2*q);
                uint32_t vg8 = wg8[cc] >> (hc*16 + 2*q);
                uint32_t a[4] = { amask(vg), amask(vg8), amask(vg >> 8), amask(vg8 >> 8) };
                if (hc == 0) { MMA16816(dacc, a, r0, r1); }
                else         { MMA16816(dacc, a, r2, r3); }
            }
        }
    }

    float* d0 = &g_part2[((size_t)s*N + i0)*8];
    *(float2*)(d0 + 2*q)       = make_float2(dacc[0], dacc[1]);
    *(float2*)(d0 + 64 + 2*q)  = make_float2(dacc[2], dacc[3]);   // row i0+8
}

// ---------------- kernel 5: reduce + relu -> out ----------------
__global__ void reduce2_kernel(float* __restrict__ out) {
    int idx = blockIdx.x*256 + threadIdx.x;   // N*8
    int i = idx >> 3;
    float sum = 0.0f;
    #pragma unroll
    for (int s = 0; s < S1; s++) sum += g_part2[(size_t)s*N*8 + idx];
    float v = sum * g_invrow[i];
    out[idx] = v > 0.0f ? v : 0.0f;
}

// ---------------- launch ----------------
extern "C" void kernel_launch(void* const* d_in, const int* in_sizes, int n_in,
                              void* d_out, int out_size) {
    const float4* led = (const float4*)d_in[0];
    const float*  B   = (const float*)d_in[1];
    const float*  emb = (const float*)d_in[2];
    const float*  W1  = (const float*)d_in[3];
    const float*  b1  = (const float*)d_in[4];
    const float*  W2  = (const float*)d_in[5];
    const float*  b2  = (const float*)d_in[6];
    float* out = (float*)d_out;

    feat_kernel<<<64, 128>>>(led, B, emb, W1, b1);
    pass1_mma<<<dim3(NIB, S1), 256>>>(led);
    reduce1_y2<<<N*32/256, 256>>>(W2, b2);
    pass2_mma<<<dim3(NIB, S1), 256>>>();
    reduce2_kernel<<<N*8/256, 256>>>(out);
}